// round 2
// baseline (speedup 1.0000x reference)
#include <cuda_runtime.h>
#include <cuda_bf16.h>
#include <math.h>

// ---------------------------------------------------------------------------
// RelNet forward:
//   img[512,3,80,80] -> 4x (conv s2 p1 + bias + relu + batchnorm(train stats))
//   -> objects [512,25,26] -> pair MLP g1..g4 (layer1 decomposed) ->
//   sum over 625 pairs -> f1 -> fc2 -> fc3 -> log_softmax -> out [512,10]
// ---------------------------------------------------------------------------

#define BATCH 512
#define FS 24
#define QDIM 11
#define HID 256
#define OBJ 25
#define EPS 1e-5f

// -------------------- scratch (device globals; no allocation) --------------
__device__ float g_buf1[BATCH * FS * 40 * 40];   // 78.6 MB
__device__ float g_buf2[BATCH * FS * 20 * 20];
__device__ float g_buf3[BATCH * FS * 10 * 10];
__device__ float g_buf4[BATCH * FS * 5 * 5];
__device__ float g_obj[BATCH * OBJ * 26];
__device__ float g_A[BATCH * OBJ * HID];
__device__ float g_B[BATCH * OBJ * HID];
__device__ float g_Cb[BATCH * HID];
__device__ float g_hA[BATCH * OBJ * OBJ * HID]; // 327.7 MB
__device__ float g_hB[BATCH * OBJ * OBJ * HID]; // 327.7 MB
__device__ float g_xg[BATCH * HID];
__device__ float g_xf1[BATCH * HID];
__device__ float g_xf2[BATCH * HID];
__device__ double g_psum[24 * 256];
__device__ double g_psq[24 * 256];
__device__ float g_stats[48]; // [0..23]=mean, [24..47]=gamma*rsqrt(var+eps)

// -------------------- conv1: Cin=3, 80 -> 40 -------------------------------
__global__ void conv1_k(const float* __restrict__ in, const float* __restrict__ w,
                        const float* __restrict__ bias, float* __restrict__ out) {
    int idx = blockIdx.x * blockDim.x + threadIdx.x;
    const int total = BATCH * FS * 40 * 40;
    if (idx >= total) return;
    int ox = idx % 40; int t = idx / 40;
    int oy = t % 40; t /= 40;
    int co = t % FS; int b = t / FS;
    float s = __ldg(&bias[co]);
    int iy0 = 2 * oy - 1, ix0 = 2 * ox - 1;
    const float* wp = w + co * 27;
    const float* ip = in + (size_t)b * 3 * 6400;
#pragma unroll
    for (int ci = 0; ci < 3; ci++) {
#pragma unroll
        for (int ky = 0; ky < 3; ky++) {
            int iy = iy0 + ky;
            if ((unsigned)iy < 80u) {
#pragma unroll
                for (int kx = 0; kx < 3; kx++) {
                    int ix = ix0 + kx;
                    if ((unsigned)ix < 80u)
                        s += __ldg(&ip[ci * 6400 + iy * 80 + ix]) * __ldg(&wp[ci * 9 + ky * 3 + kx]);
                }
            }
        }
    }
    out[idx] = fmaxf(s, 0.f);
}

// -------------------- convN: Cin=24, HIN -> HOUT ----------------------------
template <int HIN, int HOUT>
__global__ void conv24_k(const float* __restrict__ in, const float* __restrict__ w,
                         const float* __restrict__ bias, float* __restrict__ out) {
    int idx = blockIdx.x * blockDim.x + threadIdx.x;
    const int total = BATCH * FS * HOUT * HOUT;
    if (idx >= total) return;
    int ox = idx % HOUT; int t = idx / HOUT;
    int oy = t % HOUT; t /= HOUT;
    int co = t % FS; int b = t / FS;
    float s = __ldg(&bias[co]);
    int iy0 = 2 * oy - 1, ix0 = 2 * ox - 1;
    const float* wp = w + co * FS * 9;
    const float* ip = in + (size_t)b * FS * HIN * HIN;
    for (int ci = 0; ci < FS; ci++) {
        const float* ic = ip + ci * HIN * HIN;
        const float* wc = wp + ci * 9;
#pragma unroll
        for (int ky = 0; ky < 3; ky++) {
            int iy = iy0 + ky;
            if ((unsigned)iy < (unsigned)HIN) {
#pragma unroll
                for (int kx = 0; kx < 3; kx++) {
                    int ix = ix0 + kx;
                    if ((unsigned)ix < (unsigned)HIN)
                        s += __ldg(&ic[iy * HIN + ix]) * __ldg(&wc[ky * 3 + kx]);
                }
            }
        }
    }
    out[idx] = fmaxf(s, 0.f);
}

// -------------------- batchnorm stats ---------------------------------------
// grid: (24, S). Each block reduces its slice of channel c into partials.
__global__ void bn_stats_k(const float* __restrict__ x, int HW,
                           double* __restrict__ psum, double* __restrict__ psq) {
    int c = blockIdx.x;
    int s = blockIdx.y;
    int S = gridDim.y;
    long N = (long)BATCH * HW;
    long per = (N + S - 1) / S;
    long j0 = (long)s * per;
    long j1 = j0 + per; if (j1 > N) j1 = N;
    double sum = 0.0, sq = 0.0;
    for (long j = j0 + threadIdx.x; j < j1; j += blockDim.x) {
        int b = (int)(j / HW);
        int hw = (int)(j % HW);
        float v = x[((size_t)b * FS + c) * HW + hw];
        sum += v; sq += (double)v * v;
    }
    __shared__ double sh_s[256];
    __shared__ double sh_q[256];
    int tid = threadIdx.x;
    sh_s[tid] = sum; sh_q[tid] = sq;
    __syncthreads();
    for (int off = 128; off > 0; off >>= 1) {
        if (tid < off) { sh_s[tid] += sh_s[tid + off]; sh_q[tid] += sh_q[tid + off]; }
        __syncthreads();
    }
    if (tid == 0) { psum[c * 256 + s] = sh_s[0]; psq[c * 256 + s] = sh_q[0]; }
}

__global__ void bn_final_k(const double* __restrict__ psum, const double* __restrict__ psq,
                           int S, int HW, const float* __restrict__ gamma,
                           float* __restrict__ stats) {
    int c = threadIdx.x;
    if (c >= 24) return;
    double s = 0.0, q = 0.0;
    for (int i = 0; i < S; i++) { s += psum[c * 256 + i]; q += psq[c * 256 + i]; }
    double N = (double)BATCH * HW;
    double mean = s / N;
    double var = q / N - mean * mean;
    float scale = gamma[c] * rsqrtf((float)var + EPS);
    stats[c] = (float)mean;
    stats[24 + c] = scale;
}

__global__ void bn_apply_k(float* __restrict__ x, int HW, const float* __restrict__ stats,
                           const float* __restrict__ beta, int total) {
    int idx = blockIdx.x * blockDim.x + threadIdx.x;
    if (idx >= total) return;
    int c = (idx / HW) % FS;
    x[idx] = (x[idx] - stats[c]) * stats[24 + c] + beta[c];
}

// -------------------- object extraction -------------------------------------
// obj[b, o, f] : f<24 -> buf4[b, f, o]; f=24 -> ((o/5)-2)/2; f=25 -> ((o%5)-2)/2
__global__ void obj_k(const float* __restrict__ x4, float* __restrict__ obj) {
    int idx = blockIdx.x * blockDim.x + threadIdx.x;
    const int total = BATCH * OBJ * 26;
    if (idx >= total) return;
    int f = idx % 26; int t = idx / 26;
    int o = t % OBJ; int b = t / OBJ;
    float v;
    if (f < FS) v = x4[((size_t)b * FS + f) * OBJ + o];
    else if (f == FS) v = ((float)(o / 5) - 2.f) * 0.5f;
    else v = ((float)(o % 5) - 2.f) * 0.5f;
    obj[idx] = v;
}

// -------------------- g1 decomposition --------------------------------------
// A[m,n] = sum_{f<26} obj[m,f] * g1w[n,f]      (obj_i part)
// B[m,n] = sum_{f<26} obj[m,f] * g1w[n,26+f]   (obj_k part)
__global__ void ab_k(const float* __restrict__ obj, const float* __restrict__ g1w,
                     float* __restrict__ A, float* __restrict__ B) {
    int m = blockIdx.x;
    int n = threadIdx.x;
    __shared__ float os[26];
    if (n < 26) os[n] = obj[m * 26 + n];
    __syncthreads();
    const float* wr = g1w + n * 63;
    float sa = 0.f, sb = 0.f;
#pragma unroll
    for (int f = 0; f < 26; f++) {
        float o = os[f];
        sa += o * __ldg(&wr[f]);
        sb += o * __ldg(&wr[26 + f]);
    }
    A[m * HID + n] = sa;
    B[m * HID + n] = sb;
}

// Cb[b,n] = sum_{d<11} q[b,d]*g1w[n,52+d] + g1b[n], with q[b,d] = qst[d,b]
__global__ void cb_k(const float* __restrict__ qst, const float* __restrict__ g1w,
                     const float* __restrict__ g1b, float* __restrict__ Cb) {
    int b = blockIdx.x;
    int n = threadIdx.x;
    __shared__ float qs[QDIM];
    if (n < QDIM) qs[n] = qst[n * BATCH + b];
    __syncthreads();
    const float* wr = g1w + n * 63 + 52;
    float s = g1b[n];
#pragma unroll
    for (int d = 0; d < QDIM; d++) s += qs[d] * __ldg(&wr[d]);
    Cb[b * HID + n] = s;
}

// h1[b,k,i,n] = relu(A[b,i,n] + B[b,k,n] + Cb[b,n])
__global__ void h1_k(const float* __restrict__ A, const float* __restrict__ B,
                     const float* __restrict__ Cb, float* __restrict__ h1) {
    int idx = blockIdx.x * blockDim.x + threadIdx.x; // < 81,920,000 fits int32
    int n = idx & 255;
    int p = idx >> 8;
    int i = p % OBJ; int t = p / OBJ;
    int k = t % OBJ; int b = t / OBJ;
    float v = A[(size_t)(b * OBJ + i) * HID + n] + B[(size_t)(b * OBJ + k) * HID + n] +
              Cb[b * HID + n];
    h1[(size_t)idx] = fmaxf(v, 0.f);
}

// -------------------- main SGEMM: out = relu?(X[M,256] @ W[256,256]^T + b) ---
// BM=128, BN=64, BK=16, 256 threads, 8x4 per thread. M % 128 == 0.
__global__ void sgemm256(const float* __restrict__ X, const float* __restrict__ W,
                         const float* __restrict__ bias, float* __restrict__ out,
                         int doRelu) {
    __shared__ float Xs[16][128];
    __shared__ float Ws[16][64];
    int bm = blockIdx.y * 128;
    int bn = blockIdx.x * 64;
    int tid = threadIdx.x;
    int tx = tid & 15, ty = tid >> 4;
    float acc[8][4];
#pragma unroll
    for (int i = 0; i < 8; i++)
#pragma unroll
        for (int j = 0; j < 4; j++) acc[i][j] = 0.f;

    int r0 = tid >> 2;          // 0..63
    int c0 = (tid & 3) * 4;     // 0,4,8,12
    const float* Xp = X + (size_t)bm * 256;

    for (int k0 = 0; k0 < 256; k0 += 16) {
        float4 x0 = *(const float4*)(Xp + (size_t)r0 * 256 + k0 + c0);
        float4 x1 = *(const float4*)(Xp + (size_t)(r0 + 64) * 256 + k0 + c0);
        float4 wv = *(const float4*)(W + (size_t)(bn + r0) * 256 + k0 + c0);
        Xs[c0 + 0][r0] = x0.x; Xs[c0 + 1][r0] = x0.y; Xs[c0 + 2][r0] = x0.z; Xs[c0 + 3][r0] = x0.w;
        Xs[c0 + 0][r0 + 64] = x1.x; Xs[c0 + 1][r0 + 64] = x1.y; Xs[c0 + 2][r0 + 64] = x1.z; Xs[c0 + 3][r0 + 64] = x1.w;
        Ws[c0 + 0][r0] = wv.x; Ws[c0 + 1][r0] = wv.y; Ws[c0 + 2][r0] = wv.z; Ws[c0 + 3][r0] = wv.w;
        __syncthreads();
#pragma unroll
        for (int k = 0; k < 16; k++) {
            float4 a0 = *(const float4*)&Xs[k][ty * 8];
            float4 a1 = *(const float4*)&Xs[k][ty * 8 + 4];
            float4 b = *(const float4*)&Ws[k][tx * 4];
            acc[0][0] += a0.x * b.x; acc[0][1] += a0.x * b.y; acc[0][2] += a0.x * b.z; acc[0][3] += a0.x * b.w;
            acc[1][0] += a0.y * b.x; acc[1][1] += a0.y * b.y; acc[1][2] += a0.y * b.z; acc[1][3] += a0.y * b.w;
            acc[2][0] += a0.z * b.x; acc[2][1] += a0.z * b.y; acc[2][2] += a0.z * b.z; acc[2][3] += a0.z * b.w;
            acc[3][0] += a0.w * b.x; acc[3][1] += a0.w * b.y; acc[3][2] += a0.w * b.z; acc[3][3] += a0.w * b.w;
            acc[4][0] += a1.x * b.x; acc[4][1] += a1.x * b.y; acc[4][2] += a1.x * b.z; acc[4][3] += a1.x * b.w;
            acc[5][0] += a1.y * b.x; acc[5][1] += a1.y * b.y; acc[5][2] += a1.y * b.z; acc[5][3] += a1.y * b.w;
            acc[6][0] += a1.z * b.x; acc[6][1] += a1.z * b.y; acc[6][2] += a1.z * b.z; acc[6][3] += a1.z * b.w;
            acc[7][0] += a1.w * b.x; acc[7][1] += a1.w * b.y; acc[7][2] += a1.w * b.z; acc[7][3] += a1.w * b.w;
        }
        __syncthreads();
    }
    float4 bv = *(const float4*)&bias[bn + tx * 4];
#pragma unroll
    for (int i = 0; i < 8; i++) {
        int m = bm + ty * 8 + i;
        float4 v;
        v.x = acc[i][0] + bv.x; v.y = acc[i][1] + bv.y;
        v.z = acc[i][2] + bv.z; v.w = acc[i][3] + bv.w;
        if (doRelu) {
            v.x = fmaxf(v.x, 0.f); v.y = fmaxf(v.y, 0.f);
            v.z = fmaxf(v.z, 0.f); v.w = fmaxf(v.w, 0.f);
        }
        *(float4*)(out + (size_t)m * 256 + bn + tx * 4) = v;
    }
}

// -------------------- pair sum ----------------------------------------------
__global__ void pairsum_k(const float* __restrict__ h, float* __restrict__ xg) {
    int b = blockIdx.x;
    int n = threadIdx.x;
    const float* p = h + (size_t)b * (OBJ * OBJ) * HID + n;
    float s = 0.f;
    for (int j = 0; j < OBJ * OBJ; j++) s += p[(size_t)j * HID];
    xg[b * HID + n] = s;
}

// -------------------- fc3 + log_softmax -------------------------------------
__global__ void fc3_k(const float* __restrict__ x, const float* __restrict__ w,
                      const float* __restrict__ bias, float* __restrict__ out) {
    int b = blockIdx.x;
    int tid = threadIdx.x; // 320
    int j = tid >> 5, lane = tid & 31;
    __shared__ float lg[10];
    __shared__ float lse;
    const float* xr = x + b * HID;
    const float* wr = w + j * HID;
    float s = 0.f;
    for (int k = lane; k < HID; k += 32) s += xr[k] * wr[k];
#pragma unroll
    for (int o = 16; o > 0; o >>= 1) s += __shfl_xor_sync(0xffffffffu, s, o);
    if (lane == 0) lg[j] = s + bias[j];
    __syncthreads();
    if (tid == 0) {
        float m = lg[0];
#pragma unroll
        for (int t = 1; t < 10; t++) m = fmaxf(m, lg[t]);
        float se = 0.f;
#pragma unroll
        for (int t = 0; t < 10; t++) se += expf(lg[t] - m);
        lse = m + logf(se);
    }
    __syncthreads();
    if (tid < 10) out[b * 10 + tid] = lg[tid] - lse;
}

// ---------------------------------------------------------------------------
extern "C" void kernel_launch(void* const* d_in, const int* in_sizes, int n_in,
                              void* d_out, int out_size) {
    const float* img = (const float*)d_in[0];
    const float* qst = (const float*)d_in[1];
    const float* cw[4] = {(const float*)d_in[2], (const float*)d_in[6], (const float*)d_in[10], (const float*)d_in[14]};
    const float* cb[4] = {(const float*)d_in[3], (const float*)d_in[7], (const float*)d_in[11], (const float*)d_in[15]};
    const float* bg[4] = {(const float*)d_in[4], (const float*)d_in[8], (const float*)d_in[12], (const float*)d_in[16]};
    const float* bb[4] = {(const float*)d_in[5], (const float*)d_in[9], (const float*)d_in[13], (const float*)d_in[17]};
    const float* g1w = (const float*)d_in[18]; const float* g1b = (const float*)d_in[19];
    const float* g2w = (const float*)d_in[20]; const float* g2b = (const float*)d_in[21];
    const float* g3w = (const float*)d_in[22]; const float* g3b = (const float*)d_in[23];
    const float* g4w = (const float*)d_in[24]; const float* g4b = (const float*)d_in[25];
    const float* f1w = (const float*)d_in[26]; const float* f1b = (const float*)d_in[27];
    const float* fc2w = (const float*)d_in[28]; const float* fc2b = (const float*)d_in[29];
    const float* fc3w = (const float*)d_in[30]; const float* fc3b = (const float*)d_in[31];
    float* out = (float*)d_out;

    float *buf1, *buf2, *buf3, *buf4, *obj, *A, *B, *Cb, *hA, *hB, *xg, *xf1, *xf2, *stats;
    double *psum, *psq;
    cudaGetSymbolAddress((void**)&buf1, g_buf1);
    cudaGetSymbolAddress((void**)&buf2, g_buf2);
    cudaGetSymbolAddress((void**)&buf3, g_buf3);
    cudaGetSymbolAddress((void**)&buf4, g_buf4);
    cudaGetSymbolAddress((void**)&obj, g_obj);
    cudaGetSymbolAddress((void**)&A, g_A);
    cudaGetSymbolAddress((void**)&B, g_B);
    cudaGetSymbolAddress((void**)&Cb, g_Cb);
    cudaGetSymbolAddress((void**)&hA, g_hA);
    cudaGetSymbolAddress((void**)&hB, g_hB);
    cudaGetSymbolAddress((void**)&xg, g_xg);
    cudaGetSymbolAddress((void**)&xf1, g_xf1);
    cudaGetSymbolAddress((void**)&xf2, g_xf2);
    cudaGetSymbolAddress((void**)&stats, g_stats);
    cudaGetSymbolAddress((void**)&psum, g_psum);
    cudaGetSymbolAddress((void**)&psq, g_psq);

    // ---- conv stack ----
    {
        int total = BATCH * FS * 40 * 40;
        conv1_k<<<(total + 255) / 256, 256>>>(img, cw[0], cb[0], buf1);
        bn_stats_k<<<dim3(24, 256), 256>>>(buf1, 1600, psum, psq);
        bn_final_k<<<1, 32>>>(psum, psq, 256, 1600, bg[0], stats);
        bn_apply_k<<<(total + 255) / 256, 256>>>(buf1, 1600, stats, bb[0], total);
    }
    {
        int total = BATCH * FS * 20 * 20;
        conv24_k<40, 20><<<(total + 255) / 256, 256>>>(buf1, cw[1], cb[1], buf2);
        bn_stats_k<<<dim3(24, 128), 256>>>(buf2, 400, psum, psq);
        bn_final_k<<<1, 32>>>(psum, psq, 128, 400, bg[1], stats);
        bn_apply_k<<<(total + 255) / 256, 256>>>(buf2, 400, stats, bb[1], total);
    }
    {
        int total = BATCH * FS * 10 * 10;
        conv24_k<20, 10><<<(total + 255) / 256, 256>>>(buf2, cw[2], cb[2], buf3);
        bn_stats_k<<<dim3(24, 64), 256>>>(buf3, 100, psum, psq);
        bn_final_k<<<1, 32>>>(psum, psq, 64, 100, bg[2], stats);
        bn_apply_k<<<(total + 255) / 256, 256>>>(buf3, 100, stats, bb[2], total);
    }
    {
        int total = BATCH * FS * 5 * 5;
        conv24_k<10, 5><<<(total + 255) / 256, 256>>>(buf3, cw[3], cb[3], buf4);
        bn_stats_k<<<dim3(24, 16), 256>>>(buf4, 25, psum, psq);
        bn_final_k<<<1, 32>>>(psum, psq, 16, 25, bg[3], stats);
        bn_apply_k<<<(total + 255) / 256, 256>>>(buf4, 25, stats, bb[3], total);
    }

    // ---- objects + decomposed g1 ----
    {
        int total = BATCH * OBJ * 26;
        obj_k<<<(total + 255) / 256, 256>>>(buf4, obj);
    }
    ab_k<<<BATCH * OBJ, 256>>>(obj, g1w, A, B);
    cb_k<<<BATCH, 256>>>(qst, g1w, g1b, Cb);
    h1_k<<<BATCH * OBJ * OBJ, 256>>>(A, B, Cb, hA);

    // ---- g2..g4: [320000,256] x [256,256]^T ----
    dim3 ggrid(256 / 64, (BATCH * OBJ * OBJ) / 128); // (4, 2500)
    sgemm256<<<ggrid, 256>>>(hA, g2w, g2b, hB, 1);
    sgemm256<<<ggrid, 256>>>(hB, g3w, g3b, hA, 1);
    sgemm256<<<ggrid, 256>>>(hA, g4w, g4b, hB, 1);

    // ---- pair sum + f-MLP ----
    pairsum_k<<<BATCH, 256>>>(hB, xg);
    dim3 fgrid(256 / 64, BATCH / 128); // (4, 4)
    sgemm256<<<fgrid, 256>>>(xg, f1w, f1b, xf1, 1);
    sgemm256<<<fgrid, 256>>>(xf1, fc2w, fc2b, xf2, 1);
    fc3_k<<<BATCH, 320>>>(xf2, fc3w, fc3b, out);
}

// round 5
// speedup vs baseline: 1.7691x; 1.7691x over previous
#include <cuda_runtime.h>
#include <cuda_bf16.h>
#include <math.h>
#include <stdint.h>

#define BATCH 512
#define FS 24
#define QDIM 11
#define HID 256
#define OBJ 25
#define EPS 1e-5f

// -------------------- scratch (device globals; no allocation) --------------
__device__ float g_buf1[BATCH * FS * 40 * 40];
__device__ float g_buf2[BATCH * FS * 20 * 20];
__device__ float g_buf3[BATCH * FS * 10 * 10];
__device__ float g_buf4[BATCH * FS * 5 * 5];
__device__ float g_obj[BATCH * OBJ * 26];
__device__ float g_A[BATCH * OBJ * HID];
__device__ float g_B[BATCH * OBJ * HID];
__device__ float g_Cb[BATCH * HID];
__device__ __align__(16) float g_hA[BATCH * OBJ * OBJ * HID];   // 327.7 MB fp32
__device__ __align__(16) float g_hB[BATCH * OBJ * OBJ * HID];   // 327.7 MB fp32
__device__ __align__(16) float g_wt[3][HID * HID];              // tf32-rounded weights
__device__ float g_xg[BATCH * HID];
__device__ float g_xf1[BATCH * HID];
__device__ float g_xf2[BATCH * HID];
__device__ double g_psum[24 * 256];
__device__ double g_psq[24 * 256];
__device__ float g_stats[48];

// ===================== helpers ==============================================
__device__ __forceinline__ uint32_t smem_u32(const void* p) {
    uint32_t a;
    asm("{ .reg .u64 tmp; cvta.to.shared.u64 tmp, %1; cvt.u32.u64 %0, tmp; }"
        : "=r"(a) : "l"(p));
    return a;
}

#define CP_ASYNC16(dst, src) \
    asm volatile("cp.async.cg.shared.global [%0], [%1], 16;" :: "r"(dst), "l"(src))
#define CP_COMMIT() asm volatile("cp.async.commit_group;")
#define CP_WAIT1() asm volatile("cp.async.wait_group 1;")
#define CP_WAIT0() asm volatile("cp.async.wait_group 0;")

__device__ __forceinline__ float tf32r(float x) {
    uint32_t u;
    asm("cvt.rna.tf32.f32 %0, %1;" : "=r"(u) : "f"(x));
    return __uint_as_float(u);
}

__device__ __forceinline__ void mma_tf32(float* d, const uint32_t* a, const uint32_t* b) {
    asm volatile(
        "mma.sync.aligned.m16n8k8.row.col.f32.tf32.tf32.f32 "
        "{%0,%1,%2,%3}, {%4,%5,%6,%7}, {%8,%9}, {%0,%1,%2,%3};"
        : "+f"(d[0]), "+f"(d[1]), "+f"(d[2]), "+f"(d[3])
        : "r"(a[0]), "r"(a[1]), "r"(a[2]), "r"(a[3]), "r"(b[0]), "r"(b[1]));
}

// -------------------- conv1: Cin=3, 80 -> 40 -------------------------------
__global__ void conv1_k(const float* __restrict__ in, const float* __restrict__ w,
                        const float* __restrict__ bias, float* __restrict__ out) {
    int idx = blockIdx.x * blockDim.x + threadIdx.x;
    const int total = BATCH * FS * 40 * 40;
    if (idx >= total) return;
    int ox = idx % 40; int t = idx / 40;
    int oy = t % 40; t /= 40;
    int co = t % FS; int b = t / FS;
    float s = __ldg(&bias[co]);
    int iy0 = 2 * oy - 1, ix0 = 2 * ox - 1;
    const float* wp = w + co * 27;
    const float* ip = in + (size_t)b * 3 * 6400;
#pragma unroll
    for (int ci = 0; ci < 3; ci++) {
#pragma unroll
        for (int ky = 0; ky < 3; ky++) {
            int iy = iy0 + ky;
            if ((unsigned)iy < 80u) {
#pragma unroll
                for (int kx = 0; kx < 3; kx++) {
                    int ix = ix0 + kx;
                    if ((unsigned)ix < 80u)
                        s += __ldg(&ip[ci * 6400 + iy * 80 + ix]) * __ldg(&wp[ci * 9 + ky * 3 + kx]);
                }
            }
        }
    }
    out[idx] = fmaxf(s, 0.f);
}

// -------------------- convN: Cin=24 -----------------------------------------
template <int HIN, int HOUT>
__global__ void conv24_k(const float* __restrict__ in, const float* __restrict__ w,
                         const float* __restrict__ bias, float* __restrict__ out) {
    int idx = blockIdx.x * blockDim.x + threadIdx.x;
    const int total = BATCH * FS * HOUT * HOUT;
    if (idx >= total) return;
    int ox = idx % HOUT; int t = idx / HOUT;
    int oy = t % HOUT; t /= HOUT;
    int co = t % FS; int b = t / FS;
    float s = __ldg(&bias[co]);
    int iy0 = 2 * oy - 1, ix0 = 2 * ox - 1;
    const float* wp = w + co * FS * 9;
    const float* ip = in + (size_t)b * FS * HIN * HIN;
    for (int ci = 0; ci < FS; ci++) {
        const float* ic = ip + ci * HIN * HIN;
        const float* wc = wp + ci * 9;
#pragma unroll
        for (int ky = 0; ky < 3; ky++) {
            int iy = iy0 + ky;
            if ((unsigned)iy < (unsigned)HIN) {
#pragma unroll
                for (int kx = 0; kx < 3; kx++) {
                    int ix = ix0 + kx;
                    if ((unsigned)ix < (unsigned)HIN)
                        s += __ldg(&ic[iy * HIN + ix]) * __ldg(&wc[ky * 3 + kx]);
                }
            }
        }
    }
    out[idx] = fmaxf(s, 0.f);
}

// -------------------- batchnorm ---------------------------------------------
__global__ void bn_stats_k(const float* __restrict__ x, int HW,
                           double* __restrict__ psum, double* __restrict__ psq) {
    int c = blockIdx.x;
    int s = blockIdx.y;
    int S = gridDim.y;
    long N = (long)BATCH * HW;
    long per = (N + S - 1) / S;
    long j0 = (long)s * per;
    long j1 = j0 + per; if (j1 > N) j1 = N;
    double sum = 0.0, sq = 0.0;
    for (long j = j0 + threadIdx.x; j < j1; j += blockDim.x) {
        int b = (int)(j / HW);
        int hw = (int)(j % HW);
        float v = x[((size_t)b * FS + c) * HW + hw];
        sum += v; sq += (double)v * v;
    }
    __shared__ double sh_s[256];
    __shared__ double sh_q[256];
    int tid = threadIdx.x;
    sh_s[tid] = sum; sh_q[tid] = sq;
    __syncthreads();
    for (int off = 128; off > 0; off >>= 1) {
        if (tid < off) { sh_s[tid] += sh_s[tid + off]; sh_q[tid] += sh_q[tid + off]; }
        __syncthreads();
    }
    if (tid == 0) { psum[c * 256 + s] = sh_s[0]; psq[c * 256 + s] = sh_q[0]; }
}

__global__ void bn_final_k(const double* __restrict__ psum, const double* __restrict__ psq,
                           int S, int HW, const float* __restrict__ gamma,
                           float* __restrict__ stats) {
    int c = threadIdx.x;
    if (c >= 24) return;
    double s = 0.0, q = 0.0;
    for (int i = 0; i < S; i++) { s += psum[c * 256 + i]; q += psq[c * 256 + i]; }
    double N = (double)BATCH * HW;
    double mean = s / N;
    double var = q / N - mean * mean;
    float scale = gamma[c] * rsqrtf((float)var + EPS);
    stats[c] = (float)mean;
    stats[24 + c] = scale;
}

__global__ void bn_apply_k(float* __restrict__ x, int HW, const float* __restrict__ stats,
                           const float* __restrict__ beta, int total) {
    int idx = blockIdx.x * blockDim.x + threadIdx.x;
    if (idx >= total) return;
    int c = (idx / HW) % FS;
    x[idx] = (x[idx] - stats[c]) * stats[24 + c] + beta[c];
}

// -------------------- object extraction -------------------------------------
__global__ void obj_k(const float* __restrict__ x4, float* __restrict__ obj) {
    int idx = blockIdx.x * blockDim.x + threadIdx.x;
    const int total = BATCH * OBJ * 26;
    if (idx >= total) return;
    int f = idx % 26; int t = idx / 26;
    int o = t % OBJ; int b = t / OBJ;
    float v;
    if (f < FS) v = x4[((size_t)b * FS + f) * OBJ + o];
    else if (f == FS) v = ((float)(o / 5) - 2.f) * 0.5f;
    else v = ((float)(o % 5) - 2.f) * 0.5f;
    obj[idx] = v;
}

// -------------------- g1 decomposition --------------------------------------
__global__ void ab_k(const float* __restrict__ obj, const float* __restrict__ g1w,
                     float* __restrict__ A, float* __restrict__ B) {
    int m = blockIdx.x;
    int n = threadIdx.x;
    __shared__ float os[26];
    if (n < 26) os[n] = obj[m * 26 + n];
    __syncthreads();
    const float* wr = g1w + n * 63;
    float sa = 0.f, sb = 0.f;
#pragma unroll
    for (int f = 0; f < 26; f++) {
        float o = os[f];
        sa += o * __ldg(&wr[f]);
        sb += o * __ldg(&wr[26 + f]);
    }
    A[m * HID + n] = sa;
    B[m * HID + n] = sb;
}

__global__ void cb_k(const float* __restrict__ qst, const float* __restrict__ g1w,
                     const float* __restrict__ g1b, float* __restrict__ Cb) {
    int b = blockIdx.x;
    int n = threadIdx.x;
    __shared__ float qs[QDIM];
    if (n < QDIM) qs[n] = qst[n * BATCH + b];
    __syncthreads();
    const float* wr = g1w + n * 63 + 52;
    float s = g1b[n];
#pragma unroll
    for (int d = 0; d < QDIM; d++) s += qs[d] * __ldg(&wr[d]);
    Cb[b * HID + n] = s;
}

// h1[b,k,i,n] = tf32(relu(A[b,i,n] + B[b,k,n] + Cb[b,n])), 8 fp32 per thread
__global__ void h1_k(const float* __restrict__ A, const float* __restrict__ B,
                     const float* __restrict__ Cb, float* __restrict__ h1) {
    int idx = blockIdx.x * blockDim.x + threadIdx.x;
    if (idx >= BATCH * OBJ * OBJ * 32) return;
    int c = (idx & 31) * 8;
    int p = idx >> 5;
    int i = p % OBJ; int t = p / OBJ;
    int k = t % OBJ; int b = t / OBJ;
    const float4* Ap = (const float4*)(A + ((b * OBJ + i) << 8) + c);
    const float4* Bp = (const float4*)(B + ((b * OBJ + k) << 8) + c);
    const float4* Cp = (const float4*)(Cb + (b << 8) + c);
    float4 a0 = Ap[0], a1 = Ap[1];
    float4 b0 = Bp[0], b1 = Bp[1];
    float4 c0 = Cp[0], c1 = Cp[1];
    float4 o0, o1;
    o0.x = tf32r(fmaxf(a0.x + b0.x + c0.x, 0.f));
    o0.y = tf32r(fmaxf(a0.y + b0.y + c0.y, 0.f));
    o0.z = tf32r(fmaxf(a0.z + b0.z + c0.z, 0.f));
    o0.w = tf32r(fmaxf(a0.w + b0.w + c0.w, 0.f));
    o1.x = tf32r(fmaxf(a1.x + b1.x + c1.x, 0.f));
    o1.y = tf32r(fmaxf(a1.y + b1.y + c1.y, 0.f));
    o1.z = tf32r(fmaxf(a1.z + b1.z + c1.z, 0.f));
    o1.w = tf32r(fmaxf(a1.w + b1.w + c1.w, 0.f));
    float* dst = h1 + (size_t)p * 256 + c;
    *(float4*)dst = o0;
    *(float4*)(dst + 4) = o1;
}

// -------------------- weight prep: fp32 -> tf32-rounded fp32 ----------------
__global__ void wtf32_k(const float* __restrict__ w, float* __restrict__ o) {
    int idx = blockIdx.x * blockDim.x + threadIdx.x;
    if (idx < HID * HID) o[idx] = tf32r(w[idx]);
}

// ==================== tf32 mma GEMM: Y = relu(X @ W^T + b) ==================
// X[M,256] fp32(tf32), W[256,256] fp32(tf32) row-major [n][k], Y[M,256] fp32.
// Grid (2, M/128). CTA 128x128, 8 warps 64x32 each, BK=16, cp.async dbuf.
// smem rows padded to 20 floats -> conflict-free fragment gathers.
#define TPAD 20
#define TBUF (128 * TPAD)           // floats per buffer

__global__ void __launch_bounds__(256, 2)
gmlp_tf32(const float* __restrict__ X, const float* __restrict__ W,
          const float* __restrict__ bias, float* __restrict__ Y, int doRound) {
    __shared__ __align__(16) float As[2][TBUF];
    __shared__ __align__(16) float Bs[2][TBUF];
    __shared__ float biasS[128];

    const int tid = threadIdx.x;
    const int wid = tid >> 5;
    const int lane = tid & 31;
    const int wm = wid >> 2;            // 0..1
    const int wn = wid & 3;             // 0..3
    const int n0 = blockIdx.x * 128;
    const size_t mBase = (size_t)blockIdx.y * 128;

    if (tid < 128) biasS[tid] = __ldg(&bias[n0 + tid]);

    const uint32_t aRaw = smem_u32(As);
    const uint32_t bRaw = smem_u32(Bs);
    const float* Xt = X + mBase * 256;
    const float* Wt = W + (size_t)n0 * 256;

    const int lr = tid >> 1;            // 0..127
    const int lh = tid & 1;             // half of the BK=16 row (8 floats)

    auto issue = [&](int buf, int k0) {
        uint32_t ad = aRaw + buf * (TBUF * 4) + lr * (TPAD * 4) + lh * 32;
        uint32_t bd = bRaw + buf * (TBUF * 4) + lr * (TPAD * 4) + lh * 32;
        const float* xs = Xt + lr * 256 + k0 + lh * 8;
        const float* ws = Wt + lr * 256 + k0 + lh * 8;
        CP_ASYNC16(ad, xs);
        CP_ASYNC16(ad + 16, xs + 4);
        CP_ASYNC16(bd, ws);
        CP_ASYNC16(bd + 16, ws + 4);
    };

    float acc[4][4][4];
#pragma unroll
    for (int i = 0; i < 4; i++)
#pragma unroll
        for (int j = 0; j < 4; j++)
#pragma unroll
            for (int r = 0; r < 4; r++) acc[i][j][r] = 0.f;

    issue(0, 0);
    CP_COMMIT();

    const int lq = lane >> 2;           // 0..7
    const int lk = lane & 3;            // 0..3

#pragma unroll 1
    for (int kt = 0; kt < 16; kt++) {
        int buf = kt & 1;
        if (kt < 15) { issue(buf ^ 1, (kt + 1) * 16); CP_COMMIT(); CP_WAIT1(); }
        else CP_WAIT0();
        __syncthreads();

#pragma unroll
        for (int ks = 0; ks < 2; ks++) {
            int kk = ks * 8 + lk;
            uint32_t af[4][4];
#pragma unroll
            for (int mf = 0; mf < 4; mf++) {
                const float* ap = &As[buf][(wm * 64 + mf * 16 + lq) * TPAD + kk];
                af[mf][0] = __float_as_uint(ap[0]);
                af[mf][1] = __float_as_uint(ap[8 * TPAD]);
                af[mf][2] = __float_as_uint(ap[4]);
                af[mf][3] = __float_as_uint(ap[8 * TPAD + 4]);
            }
            uint32_t bfr[4][2];
#pragma unroll
            for (int nf = 0; nf < 4; nf++) {
                const float* bp = &Bs[buf][(wn * 32 + nf * 8 + lq) * TPAD + kk];
                bfr[nf][0] = __float_as_uint(bp[0]);
                bfr[nf][1] = __float_as_uint(bp[4]);
            }
#pragma unroll
            for (int mf = 0; mf < 4; mf++)
#pragma unroll
                for (int nf = 0; nf < 4; nf++)
                    mma_tf32(acc[mf][nf], af[mf], bfr[nf]);
        }
        __syncthreads();
    }

    // epilogue: + bias, relu, optional tf32 round, store fp32
#pragma unroll
    for (int mf = 0; mf < 4; mf++) {
        size_t r0 = mBase + wm * 64 + mf * 16 + lq;
        float* y0 = Y + r0 * 256 + n0;
        float* y1 = y0 + 8 * 256;
#pragma unroll
        for (int nf = 0; nf < 4; nf++) {
            int col = wn * 32 + nf * 8 + 2 * lk;
            float b0 = biasS[col], b1 = biasS[col + 1];
            float v0 = fmaxf(acc[mf][nf][0] + b0, 0.f);
            float v1 = fmaxf(acc[mf][nf][1] + b1, 0.f);
            float v2 = fmaxf(acc[mf][nf][2] + b0, 0.f);
            float v3 = fmaxf(acc[mf][nf][3] + b1, 0.f);
            if (doRound) {
                v0 = tf32r(v0); v1 = tf32r(v1);
                v2 = tf32r(v2); v3 = tf32r(v3);
            }
            float2 p0 = {v0, v1};
            float2 p1 = {v2, v3};
            *(float2*)(y0 + col) = p0;
            *(float2*)(y1 + col) = p1;
        }
    }
}

// -------------------- pair sum ----------------------------------------------
__global__ void pairsum_k(const float* __restrict__ h, float* __restrict__ xg) {
    int b = blockIdx.x;
    int n = threadIdx.x;
    const float* p = h + (size_t)b * (OBJ * OBJ) * HID + n;
    float s = 0.f;
    for (int j = 0; j < OBJ * OBJ; j++) s += p[(size_t)j * HID];
    xg[b * HID + n] = s;
}

// -------------------- fp32 SGEMM (small f-layers) ---------------------------
__global__ void sgemm256(const float* __restrict__ X, const float* __restrict__ W,
                         const float* __restrict__ bias, float* __restrict__ out,
                         int doRelu) {
    __shared__ float Xs[16][128];
    __shared__ float Ws[16][64];
    int bm = blockIdx.y * 128;
    int bn = blockIdx.x * 64;
    int tid = threadIdx.x;
    int tx = tid & 15, ty = tid >> 4;
    float acc[8][4];
#pragma unroll
    for (int i = 0; i < 8; i++)
#pragma unroll
        for (int j = 0; j < 4; j++) acc[i][j] = 0.f;

    int r0 = tid >> 2;
    int c0 = (tid & 3) * 4;
    const float* Xp = X + (size_t)bm * 256;

    for (int k0 = 0; k0 < 256; k0 += 16) {
        float4 x0 = *(const float4*)(Xp + (size_t)r0 * 256 + k0 + c0);
        float4 x1 = *(const float4*)(Xp + (size_t)(r0 + 64) * 256 + k0 + c0);
        float4 wv = *(const float4*)(W + (size_t)(bn + r0) * 256 + k0 + c0);
        Xs[c0 + 0][r0] = x0.x; Xs[c0 + 1][r0] = x0.y; Xs[c0 + 2][r0] = x0.z; Xs[c0 + 3][r0] = x0.w;
        Xs[c0 + 0][r0 + 64] = x1.x; Xs[c0 + 1][r0 + 64] = x1.y; Xs[c0 + 2][r0 + 64] = x1.z; Xs[c0 + 3][r0 + 64] = x1.w;
        Ws[c0 + 0][r0] = wv.x; Ws[c0 + 1][r0] = wv.y; Ws[c0 + 2][r0] = wv.z; Ws[c0 + 3][r0] = wv.w;
        __syncthreads();
#pragma unroll
        for (int k = 0; k < 16; k++) {
            float4 a0 = *(const float4*)&Xs[k][ty * 8];
            float4 a1 = *(const float4*)&Xs[k][ty * 8 + 4];
            float4 b = *(const float4*)&Ws[k][tx * 4];
            acc[0][0] += a0.x * b.x; acc[0][1] += a0.x * b.y; acc[0][2] += a0.x * b.z; acc[0][3] += a0.x * b.w;
            acc[1][0] += a0.y * b.x; acc[1][1] += a0.y * b.y; acc[1][2] += a0.y * b.z; acc[1][3] += a0.y * b.w;
            acc[2][0] += a0.z * b.x; acc[2][1] += a0.z * b.y; acc[2][2] += a0.z * b.z; acc[2][3] += a0.z * b.w;
            acc[3][0] += a0.w * b.x; acc[3][1] += a0.w * b.y; acc[3][2] += a0.w * b.z; acc[3][3] += a0.w * b.w;
            acc[4][0] += a1.x * b.x; acc[4][1] += a1.x * b.y; acc[4][2] += a1.x * b.z; acc[4][3] += a1.x * b.w;
            acc[5][0] += a1.y * b.x; acc[5][1] += a1.y * b.y; acc[5][2] += a1.y * b.z; acc[5][3] += a1.y * b.w;
            acc[6][0] += a1.z * b.x; acc[6][1] += a1.z * b.y; acc[6][2] += a1.z * b.z; acc[6][3] += a1.z * b.w;
            acc[7][0] += a1.w * b.x; acc[7][1] += a1.w * b.y; acc[7][2] += a1.w * b.z; acc[7][3] += a1.w * b.w;
        }
        __syncthreads();
    }
    float4 bv = *(const float4*)&bias[bn + tx * 4];
#pragma unroll
    for (int i = 0; i < 8; i++) {
        int m = bm + ty * 8 + i;
        float4 v;
        v.x = acc[i][0] + bv.x; v.y = acc[i][1] + bv.y;
        v.z = acc[i][2] + bv.z; v.w = acc[i][3] + bv.w;
        if (doRelu) {
            v.x = fmaxf(v.x, 0.f); v.y = fmaxf(v.y, 0.f);
            v.z = fmaxf(v.z, 0.f); v.w = fmaxf(v.w, 0.f);
        }
        *(float4*)(out + (size_t)m * 256 + bn + tx * 4) = v;
    }
}

// -------------------- fc3 + log_softmax -------------------------------------
__global__ void fc3_k(const float* __restrict__ x, const float* __restrict__ w,
                      const float* __restrict__ bias, float* __restrict__ out) {
    int b = blockIdx.x;
    int tid = threadIdx.x; // 320
    int j = tid >> 5, lane = tid & 31;
    __shared__ float lg[10];
    __shared__ float lse;
    const float* xr = x + b * HID;
    const float* wr = w + j * HID;
    float s = 0.f;
    for (int k = lane; k < HID; k += 32) s += xr[k] * wr[k];
#pragma unroll
    for (int o = 16; o > 0; o >>= 1) s += __shfl_xor_sync(0xffffffffu, s, o);
    if (lane == 0) lg[j] = s + bias[j];
    __syncthreads();
    if (tid == 0) {
        float m = lg[0];
#pragma unroll
        for (int t = 1; t < 10; t++) m = fmaxf(m, lg[t]);
        float se = 0.f;
#pragma unroll
        for (int t = 0; t < 10; t++) se += expf(lg[t] - m);
        lse = m + logf(se);
    }
    __syncthreads();
    if (tid < 10) out[b * 10 + tid] = lg[tid] - lse;
}

// ---------------------------------------------------------------------------
extern "C" void kernel_launch(void* const* d_in, const int* in_sizes, int n_in,
                              void* d_out, int out_size) {
    const float* img = (const float*)d_in[0];
    const float* qst = (const float*)d_in[1];
    const float* cw[4] = {(const float*)d_in[2], (const float*)d_in[6], (const float*)d_in[10], (const float*)d_in[14]};
    const float* cb[4] = {(const float*)d_in[3], (const float*)d_in[7], (const float*)d_in[11], (const float*)d_in[15]};
    const float* bg[4] = {(const float*)d_in[4], (const float*)d_in[8], (const float*)d_in[12], (const float*)d_in[16]};
    const float* bb[4] = {(const float*)d_in[5], (const float*)d_in[9], (const float*)d_in[13], (const float*)d_in[17]};
    const float* g1w = (const float*)d_in[18]; const float* g1b = (const float*)d_in[19];
    const float* g2w = (const float*)d_in[20]; const float* g2b = (const float*)d_in[21];
    const float* g3w = (const float*)d_in[22]; const float* g3b = (const float*)d_in[23];
    const float* g4w = (const float*)d_in[24]; const float* g4b = (const float*)d_in[25];
    const float* f1w = (const float*)d_in[26]; const float* f1b = (const float*)d_in[27];
    const float* fc2w = (const float*)d_in[28]; const float* fc2b = (const float*)d_in[29];
    const float* fc3w = (const float*)d_in[30]; const float* fc3b = (const float*)d_in[31];
    float* out = (float*)d_out;

    float *buf1, *buf2, *buf3, *buf4, *obj, *A, *B, *Cb, *hA, *hB, *xg, *xf1, *xf2, *stats, *wt;
    double *psum, *psq;
    cudaGetSymbolAddress((void**)&buf1, g_buf1);
    cudaGetSymbolAddress((void**)&buf2, g_buf2);
    cudaGetSymbolAddress((void**)&buf3, g_buf3);
    cudaGetSymbolAddress((void**)&buf4, g_buf4);
    cudaGetSymbolAddress((void**)&obj, g_obj);
    cudaGetSymbolAddress((void**)&A, g_A);
    cudaGetSymbolAddress((void**)&B, g_B);
    cudaGetSymbolAddress((void**)&Cb, g_Cb);
    cudaGetSymbolAddress((void**)&hA, g_hA);
    cudaGetSymbolAddress((void**)&hB, g_hB);
    cudaGetSymbolAddress((void**)&xg, g_xg);
    cudaGetSymbolAddress((void**)&xf1, g_xf1);
    cudaGetSymbolAddress((void**)&xf2, g_xf2);
    cudaGetSymbolAddress((void**)&stats, g_stats);
    cudaGetSymbolAddress((void**)&psum, g_psum);
    cudaGetSymbolAddress((void**)&psq, g_psq);
    cudaGetSymbolAddress((void**)&wt, g_wt);

    // ---- conv stack ----
    {
        int total = BATCH * FS * 40 * 40;
        conv1_k<<<(total + 255) / 256, 256>>>(img, cw[0], cb[0], buf1);
        bn_stats_k<<<dim3(24, 256), 256>>>(buf1, 1600, psum, psq);
        bn_final_k<<<1, 32>>>(psum, psq, 256, 1600, bg[0], stats);
        bn_apply_k<<<(total + 255) / 256, 256>>>(buf1, 1600, stats, bb[0], total);
    }
    {
        int total = BATCH * FS * 20 * 20;
        conv24_k<40, 20><<<(total + 255) / 256, 256>>>(buf1, cw[1], cb[1], buf2);
        bn_stats_k<<<dim3(24, 128), 256>>>(buf2, 400, psum, psq);
        bn_final_k<<<1, 32>>>(psum, psq, 128, 400, bg[1], stats);
        bn_apply_k<<<(total + 255) / 256, 256>>>(buf2, 400, stats, bb[1], total);
    }
    {
        int total = BATCH * FS * 10 * 10;
        conv24_k<20, 10><<<(total + 255) / 256, 256>>>(buf2, cw[2], cb[2], buf3);
        bn_stats_k<<<dim3(24, 64), 256>>>(buf3, 100, psum, psq);
        bn_final_k<<<1, 32>>>(psum, psq, 64, 100, bg[2], stats);
        bn_apply_k<<<(total + 255) / 256, 256>>>(buf3, 100, stats, bb[2], total);
    }
    {
        int total = BATCH * FS * 5 * 5;
        conv24_k<10, 5><<<(total + 255) / 256, 256>>>(buf3, cw[3], cb[3], buf4);
        bn_stats_k<<<dim3(24, 16), 256>>>(buf4, 25, psum, psq);
        bn_final_k<<<1, 32>>>(psum, psq, 16, 25, bg[3], stats);
        bn_apply_k<<<(total + 255) / 256, 256>>>(buf4, 25, stats, bb[3], total);
    }

    // ---- weight prep (tf32 rounding) ----
    wtf32_k<<<256, 256>>>(g2w, wt);
    wtf32_k<<<256, 256>>>(g3w, wt + HID * HID);
    wtf32_k<<<256, 256>>>(g4w, wt + 2 * HID * HID);

    // ---- objects + decomposed g1 ----
    {
        int total = BATCH * OBJ * 26;
        obj_k<<<(total + 255) / 256, 256>>>(buf4, obj);
    }
    ab_k<<<BATCH * OBJ, 256>>>(obj, g1w, A, B);
    cb_k<<<BATCH, 256>>>(qst, g1w, g1b, Cb);
    h1_k<<<BATCH * OBJ * OBJ * 32 / 256, 256>>>(A, B, Cb, hA);

    // ---- g2..g4 on tensor cores (tf32 mma) ----
    dim3 ggrid(2, BATCH * OBJ * OBJ / 128);  // (2, 2500)
    gmlp_tf32<<<ggrid, 256>>>(hA, wt, g2b, hB, 1);
    gmlp_tf32<<<ggrid, 256>>>(hB, wt + HID * HID, g3b, hA, 1);
    gmlp_tf32<<<ggrid, 256>>>(hA, wt + 2 * HID * HID, g4b, hB, 0);

    // ---- pair sum + f-MLP (fp32) ----
    pairsum_k<<<BATCH, 256>>>(hB, xg);
    dim3 fgrid(256 / 64, BATCH / 128);
    sgemm256<<<fgrid, 256>>>(xg, f1w, f1b, xf1, 1);
    sgemm256<<<fgrid, 256>>>(xf1, fc2w, fc2b, xf2, 1);
    fc3_k<<<BATCH, 320>>>(xf2, fc3w, fc3b, out);
}

// round 6
// speedup vs baseline: 2.6308x; 1.4871x over previous
#include <cuda_runtime.h>
#include <cuda_bf16.h>
#include <math.h>
#include <stdint.h>

#define BATCH 512
#define FS 24
#define QDIM 11
#define HID 256
#define OBJ 25
#define EPS 1e-5f

// -------------------- scratch (device globals; no allocation) --------------
__device__ float g_buf1[BATCH * FS * 40 * 40];   // raw relu(conv+b), pre-BN
__device__ float g_buf2[BATCH * FS * 20 * 20];
__device__ float g_buf3[BATCH * FS * 10 * 10];
__device__ float g_buf4[BATCH * FS * 5 * 5];
__device__ float g_obj[BATCH * OBJ * 26];
__device__ float g_A[BATCH * OBJ * HID];
__device__ float g_B[BATCH * OBJ * HID];
__device__ float g_Cb[BATCH * HID];
__device__ __align__(16) float g_hA[BATCH * OBJ * OBJ * HID];   // g3 out
__device__ __align__(16) float g_hB[BATCH * OBJ * OBJ * HID];   // g2 out
__device__ __align__(16) float g_wt[3][HID * HID];              // tf32 weights
__device__ float g_xg[BATCH * HID];
__device__ float g_xf1[BATCH * HID];
__device__ float g_xf2[BATCH * HID];
__device__ double g_psum[4 * 24];
__device__ double g_psq[4 * 24];
__device__ float g_stats[4 * 48];   // per layer: [0..23]=mean, [24..47]=gamma*rsqrt(var+eps)

// ===================== helpers ==============================================
__device__ __forceinline__ uint32_t smem_u32(const void* p) {
    uint32_t a;
    asm("{ .reg .u64 tmp; cvta.to.shared.u64 tmp, %1; cvt.u32.u64 %0, tmp; }"
        : "=r"(a) : "l"(p));
    return a;
}

#define CP_ASYNC16(dst, src) \
    asm volatile("cp.async.cg.shared.global [%0], [%1], 16;" :: "r"(dst), "l"(src))
#define CP_COMMIT() asm volatile("cp.async.commit_group;")
#define CP_WAIT1() asm volatile("cp.async.wait_group 1;")
#define CP_WAIT0() asm volatile("cp.async.wait_group 0;")

__device__ __forceinline__ float tf32r(float x) {
    uint32_t u;
    asm("cvt.rna.tf32.f32 %0, %1;" : "=r"(u) : "f"(x));
    return __uint_as_float(u);
}

__device__ __forceinline__ void mma_tf32(float* d, const uint32_t* a, const uint32_t* b) {
    asm volatile(
        "mma.sync.aligned.m16n8k8.row.col.f32.tf32.tf32.f32 "
        "{%0,%1,%2,%3}, {%4,%5,%6,%7}, {%8,%9}, {%0,%1,%2,%3};"
        : "+f"(d[0]), "+f"(d[1]), "+f"(d[2]), "+f"(d[3])
        : "r"(a[0]), "r"(a[1]), "r"(a[2]), "r"(a[3]), "r"(b[0]), "r"(b[1]));
}

// -------------------- zero kernels ------------------------------------------
__global__ void zerof_k(float* p, int n) {
    int i = blockIdx.x * blockDim.x + threadIdx.x;
    if (i < n) p[i] = 0.f;
}
__global__ void zerod_k(double* p, int n) {
    int i = blockIdx.x * blockDim.x + threadIdx.x;
    if (i < n) p[i] = 0.0;
}

// -------------------- conv1: Cin=3, 80->40, fused stats ---------------------
// thread = one output pixel, computes all 24 channels. Stats accumulated.
__global__ void __launch_bounds__(256)
conv1_f(const float* __restrict__ in, const float* __restrict__ w,
        const float* __restrict__ bias, float* __restrict__ out,
        double* __restrict__ psum, double* __restrict__ psq) {
    __shared__ float ws[648];
    __shared__ float bs[24];
    __shared__ float srs[8][24];
    __shared__ float srq[8][24];
    int tid = threadIdx.x;
    for (int i = tid; i < 648; i += 256) ws[i] = w[i];
    if (tid < 24) bs[tid] = bias[tid];
    __syncthreads();

    int idx = blockIdx.x * 256 + tid;      // < 512*1600
    int pix = idx % 1600;
    int b = idx / 1600;
    int oy = pix / 40, ox = pix % 40;
    int iy0 = 2 * oy - 1, ix0 = 2 * ox - 1;

    float acc[24];
#pragma unroll
    for (int c = 0; c < 24; c++) acc[c] = bs[c];

    const float* ip = in + (size_t)b * 3 * 6400;
#pragma unroll
    for (int ci = 0; ci < 3; ci++) {
#pragma unroll
        for (int ky = 0; ky < 3; ky++) {
            int iy = iy0 + ky;
            bool vy = (unsigned)iy < 80u;
#pragma unroll
            for (int kx = 0; kx < 3; kx++) {
                int ix = ix0 + kx;
                float v = (vy && (unsigned)ix < 80u) ? ip[ci * 6400 + iy * 80 + ix] : 0.f;
                int t = ci * 9 + ky * 3 + kx;
#pragma unroll
                for (int co = 0; co < 24; co++)
                    acc[co] = fmaf(v, ws[co * 27 + t], acc[co]);
            }
        }
    }

    int wid = tid >> 5, lane = tid & 31;
    float* op = out + (size_t)b * 24 * 1600 + pix;
#pragma unroll
    for (int co = 0; co < 24; co++) {
        float y = fmaxf(acc[co], 0.f);
        op[co * 1600] = y;
        float s = y, q = y * y;
#pragma unroll
        for (int off = 16; off > 0; off >>= 1) {
            s += __shfl_xor_sync(0xffffffffu, s, off);
            q += __shfl_xor_sync(0xffffffffu, q, off);
        }
        if (lane == 0) { srs[wid][co] = s; srq[wid][co] = q; }
    }
    __syncthreads();
    if (tid < 24) {
        double S = 0.0, Q = 0.0;
#pragma unroll
        for (int wk = 0; wk < 8; wk++) { S += srs[wk][tid]; Q += srq[wk][tid]; }
        atomicAdd(&psum[tid], S);
        atomicAdd(&psq[tid], Q);
    }
}

// -------------------- convN: Cin=24, input-BN fused, stats fused ------------
template <int HIN, int HOUT>
__global__ void __launch_bounds__(256)
conv24_f(const float* __restrict__ in, const float* __restrict__ w,
         const float* __restrict__ bias,
         const float* __restrict__ statsPrev, const float* __restrict__ betaPrev,
         float* __restrict__ out,
         double* __restrict__ psum, double* __restrict__ psq) {
    __shared__ float ws[5184];
    __shared__ float bs[24];
    __shared__ float ab[24];   // scale of prev BN
    __shared__ float dd[24];   // beta - mean*scale
    __shared__ float srs[8][24];
    __shared__ float srq[8][24];
    int tid = threadIdx.x;
    for (int i = tid; i < 5184; i += 256) ws[i] = w[i];
    if (tid < 24) {
        bs[tid] = bias[tid];
        float sc = statsPrev[24 + tid];
        ab[tid] = sc;
        dd[tid] = betaPrev[tid] - statsPrev[tid] * sc;
    }
    __syncthreads();

    const int PIX = HOUT * HOUT;
    int idx = blockIdx.x * 256 + tid;
    int pix = idx % PIX;
    int b = idx / PIX;
    int oy = pix / HOUT, ox = pix % HOUT;
    int iy0 = 2 * oy - 1, ix0 = 2 * ox - 1;

    float acc[24];
#pragma unroll
    for (int c = 0; c < 24; c++) acc[c] = bs[c];

    const float* ip = in + (size_t)b * 24 * HIN * HIN;
    for (int ci = 0; ci < 24; ci++) {
        float ai = ab[ci], di = dd[ci];
        const float* ic = ip + ci * HIN * HIN;
#pragma unroll
        for (int ky = 0; ky < 3; ky++) {
            int iy = iy0 + ky;
            bool vy = (unsigned)iy < (unsigned)HIN;
#pragma unroll
            for (int kx = 0; kx < 3; kx++) {
                int ix = ix0 + kx;
                float v = 0.f;
                if (vy && (unsigned)ix < (unsigned)HIN)
                    v = fmaf(ic[iy * HIN + ix], ai, di);
                int t = ci * 9 + ky * 3 + kx;
#pragma unroll
                for (int co = 0; co < 24; co++)
                    acc[co] = fmaf(v, ws[co * 216 + t], acc[co]);
            }
        }
    }

    int wid = tid >> 5, lane = tid & 31;
    float* op = out + (size_t)b * 24 * PIX + pix;
#pragma unroll
    for (int co = 0; co < 24; co++) {
        float y = fmaxf(acc[co], 0.f);
        op[co * PIX] = y;
        float s = y, q = y * y;
#pragma unroll
        for (int off = 16; off > 0; off >>= 1) {
            s += __shfl_xor_sync(0xffffffffu, s, off);
            q += __shfl_xor_sync(0xffffffffu, q, off);
        }
        if (lane == 0) { srs[wid][co] = s; srq[wid][co] = q; }
    }
    __syncthreads();
    if (tid < 24) {
        double S = 0.0, Q = 0.0;
#pragma unroll
        for (int wk = 0; wk < 8; wk++) { S += srs[wk][tid]; Q += srq[wk][tid]; }
        atomicAdd(&psum[tid], S);
        atomicAdd(&psq[tid], Q);
    }
}

// -------------------- finalize BN stats -------------------------------------
__global__ void bn_final_f(const double* __restrict__ psum, const double* __restrict__ psq,
                           double N, const float* __restrict__ gamma,
                           float* __restrict__ stats) {
    int c = threadIdx.x;
    if (c >= 24) return;
    double mean = psum[c] / N;
    double var = psq[c] / N - mean * mean;
    stats[c] = (float)mean;
    stats[24 + c] = gamma[c] * rsqrtf((float)var + EPS);
}

// -------------------- object extraction (applies BN4) -----------------------
__global__ void obj_f(const float* __restrict__ x4, const float* __restrict__ stats4,
                      const float* __restrict__ beta4, float* __restrict__ obj) {
    int idx = blockIdx.x * blockDim.x + threadIdx.x;
    const int total = BATCH * OBJ * 26;
    if (idx >= total) return;
    int f = idx % 26; int t = idx / 26;
    int o = t % OBJ; int b = t / OBJ;
    float v;
    if (f < FS) {
        float y = x4[((size_t)b * FS + f) * OBJ + o];
        v = (y - stats4[f]) * stats4[24 + f] + beta4[f];
    } else if (f == FS) v = ((float)(o / 5) - 2.f) * 0.5f;
    else v = ((float)(o % 5) - 2.f) * 0.5f;
    obj[idx] = v;
}

// -------------------- g1 decomposition --------------------------------------
__global__ void ab_k(const float* __restrict__ obj, const float* __restrict__ g1w,
                     float* __restrict__ A, float* __restrict__ B) {
    int m = blockIdx.x;
    int n = threadIdx.x;
    __shared__ float os[26];
    if (n < 26) os[n] = obj[m * 26 + n];
    __syncthreads();
    const float* wr = g1w + n * 63;
    float sa = 0.f, sb = 0.f;
#pragma unroll
    for (int f = 0; f < 26; f++) {
        float o = os[f];
        sa += o * __ldg(&wr[f]);
        sb += o * __ldg(&wr[26 + f]);
    }
    A[m * HID + n] = sa;
    B[m * HID + n] = sb;
}

__global__ void cb_k(const float* __restrict__ qst, const float* __restrict__ g1w,
                     const float* __restrict__ g1b, float* __restrict__ Cb) {
    int b = blockIdx.x;
    int n = threadIdx.x;
    __shared__ float qs[QDIM];
    if (n < QDIM) qs[n] = qst[n * BATCH + b];
    __syncthreads();
    const float* wr = g1w + n * 63 + 52;
    float s = g1b[n];
#pragma unroll
    for (int d = 0; d < QDIM; d++) s += qs[d] * __ldg(&wr[d]);
    Cb[b * HID + n] = s;
}

// -------------------- weight prep: fp32 -> tf32-rounded fp32 ----------------
__global__ void wtf32_k(const float* __restrict__ w, float* __restrict__ o) {
    int idx = blockIdx.x * blockDim.x + threadIdx.x;
    if (idx < HID * HID) o[idx] = tf32r(w[idx]);
}

// ==================== tf32 mma GEMM (generic, g3): Y = relu(X W^T + b) ======
#define TPAD 20
#define TBUF (128 * TPAD)

__global__ void __launch_bounds__(256, 2)
gmlp_tf32(const float* __restrict__ X, const float* __restrict__ W,
          const float* __restrict__ bias, float* __restrict__ Y, int doRound) {
    __shared__ __align__(16) float As[2][TBUF];
    __shared__ __align__(16) float Bs[2][TBUF];
    __shared__ float biasS[128];

    const int tid = threadIdx.x;
    const int wid = tid >> 5;
    const int lane = tid & 31;
    const int wm = wid >> 2;
    const int wn = wid & 3;
    const int n0 = blockIdx.x * 128;
    const size_t mBase = (size_t)blockIdx.y * 128;

    if (tid < 128) biasS[tid] = __ldg(&bias[n0 + tid]);

    const uint32_t aRaw = smem_u32(As);
    const uint32_t bRaw = smem_u32(Bs);
    const float* Xt = X + mBase * 256;
    const float* Wt = W + (size_t)n0 * 256;

    const int lr = tid >> 1;
    const int lh = tid & 1;

    auto issue = [&](int buf, int k0) {
        uint32_t ad = aRaw + buf * (TBUF * 4) + lr * (TPAD * 4) + lh * 32;
        uint32_t bd = bRaw + buf * (TBUF * 4) + lr * (TPAD * 4) + lh * 32;
        const float* xs = Xt + lr * 256 + k0 + lh * 8;
        const float* wsrc = Wt + lr * 256 + k0 + lh * 8;
        CP_ASYNC16(ad, xs);
        CP_ASYNC16(ad + 16, xs + 4);
        CP_ASYNC16(bd, wsrc);
        CP_ASYNC16(bd + 16, wsrc + 4);
    };

    float acc[4][4][4];
#pragma unroll
    for (int i = 0; i < 4; i++)
#pragma unroll
        for (int j = 0; j < 4; j++)
#pragma unroll
            for (int r = 0; r < 4; r++) acc[i][j][r] = 0.f;

    issue(0, 0);
    CP_COMMIT();

    const int lq = lane >> 2;
    const int lk = lane & 3;

#pragma unroll 1
    for (int kt = 0; kt < 16; kt++) {
        int buf = kt & 1;
        if (kt < 15) { issue(buf ^ 1, (kt + 1) * 16); CP_COMMIT(); CP_WAIT1(); }
        else CP_WAIT0();
        __syncthreads();

#pragma unroll
        for (int ks = 0; ks < 2; ks++) {
            int kk = ks * 8 + lk;
            uint32_t af[4][4];
#pragma unroll
            for (int mf = 0; mf < 4; mf++) {
                const float* ap = &As[buf][(wm * 64 + mf * 16 + lq) * TPAD + kk];
                af[mf][0] = __float_as_uint(ap[0]);
                af[mf][1] = __float_as_uint(ap[8 * TPAD]);
                af[mf][2] = __float_as_uint(ap[4]);
                af[mf][3] = __float_as_uint(ap[8 * TPAD + 4]);
            }
            uint32_t bfr[4][2];
#pragma unroll
            for (int nf = 0; nf < 4; nf++) {
                const float* bp = &Bs[buf][(wn * 32 + nf * 8 + lq) * TPAD + kk];
                bfr[nf][0] = __float_as_uint(bp[0]);
                bfr[nf][1] = __float_as_uint(bp[4]);
            }
#pragma unroll
            for (int mf = 0; mf < 4; mf++)
#pragma unroll
                for (int nf = 0; nf < 4; nf++)
                    mma_tf32(acc[mf][nf], af[mf], bfr[nf]);
        }
        __syncthreads();
    }

#pragma unroll
    for (int mf = 0; mf < 4; mf++) {
        size_t r0 = mBase + wm * 64 + mf * 16 + lq;
        float* y0 = Y + r0 * 256 + n0;
        float* y1 = y0 + 8 * 256;
#pragma unroll
        for (int nf = 0; nf < 4; nf++) {
            int col = wn * 32 + nf * 8 + 2 * lk;
            float b0 = biasS[col], b1 = biasS[col + 1];
            float v0 = fmaxf(acc[mf][nf][0] + b0, 0.f);
            float v1 = fmaxf(acc[mf][nf][1] + b1, 0.f);
            float v2 = fmaxf(acc[mf][nf][2] + b0, 0.f);
            float v3 = fmaxf(acc[mf][nf][3] + b1, 0.f);
            if (doRound) {
                v0 = tf32r(v0); v1 = tf32r(v1);
                v2 = tf32r(v2); v3 = tf32r(v3);
            }
            float2 p0 = {v0, v1};
            float2 p1 = {v2, v3};
            *(float2*)(y0 + col) = p0;
            *(float2*)(y1 + col) = p1;
        }
    }
}

// ==================== g2: fused h1 build + tf32 GEMM ========================
// A-tile built in smem from A/B/Cb (h1 = tf32(relu(A_i + B_k + Cq))).
// smem: h1s[128*260] + Ws[2][128*20] + bias[128]. 1 CTA/SM.
#define L2PAD 260
#define GL2_SMEM ((128 * L2PAD + 2 * 128 * TPAD + 128) * 4)

__global__ void __launch_bounds__(256, 1)
gmlp_l2(const float* __restrict__ Ag, const float* __restrict__ Bg,
        const float* __restrict__ Cg, const float* __restrict__ W,
        const float* __restrict__ bias, float* __restrict__ Y) {
    extern __shared__ float sm[];
    float* h1s = sm;
    float* Ws = sm + 128 * L2PAD;
    float* biasS = Ws + 2 * 128 * TPAD;

    const int tid = threadIdx.x;
    const int wid = tid >> 5;
    const int lane = tid & 31;
    const int wm = wid >> 2;
    const int wn = wid & 3;
    const int n0 = blockIdx.x * 128;
    const size_t mBase = (size_t)blockIdx.y * 128;

    if (tid < 128) biasS[tid] = __ldg(&bias[n0 + tid]);

    // ---- build h1 tile ----
    const int lr = tid >> 1;
    const int lh = tid & 1;
    {
        int r = (int)mBase + lr;
        int b = r / 625;
        int rem = r - b * 625;
        int ko = rem / 25;
        int ii = rem - ko * 25;
        const float4* pA = (const float4*)(Ag + (b * 25 + ii) * 256);
        const float4* pB = (const float4*)(Bg + (b * 25 + ko) * 256);
        const float4* pC = (const float4*)(Cg + b * 256);
#pragma unroll 4
        for (int j = 0; j < 16; j++) {
            int col = lh * 8 + j * 16;
            int c4 = col >> 2;
            float4 a0 = __ldg(pA + c4), a1 = __ldg(pA + c4 + 1);
            float4 b0 = __ldg(pB + c4), b1 = __ldg(pB + c4 + 1);
            float4 c0 = __ldg(pC + c4), c1 = __ldg(pC + c4 + 1);
            float4 o0, o1;
            o0.x = tf32r(fmaxf(a0.x + b0.x + c0.x, 0.f));
            o0.y = tf32r(fmaxf(a0.y + b0.y + c0.y, 0.f));
            o0.z = tf32r(fmaxf(a0.z + b0.z + c0.z, 0.f));
            o0.w = tf32r(fmaxf(a0.w + b0.w + c0.w, 0.f));
            o1.x = tf32r(fmaxf(a1.x + b1.x + c1.x, 0.f));
            o1.y = tf32r(fmaxf(a1.y + b1.y + c1.y, 0.f));
            o1.z = tf32r(fmaxf(a1.z + b1.z + c1.z, 0.f));
            o1.w = tf32r(fmaxf(a1.w + b1.w + c1.w, 0.f));
            *(float4*)&h1s[lr * L2PAD + col] = o0;
            *(float4*)&h1s[lr * L2PAD + col + 4] = o1;
        }
    }

    const float* Wt = W + (size_t)n0 * 256;
    const uint32_t wRaw = smem_u32(Ws);
    auto issue = [&](int buf, int k0) {
        uint32_t bd = wRaw + buf * (128 * TPAD * 4) + lr * (TPAD * 4) + lh * 32;
        const float* wsrc = Wt + lr * 256 + k0 + lh * 8;
        CP_ASYNC16(bd, wsrc);
        CP_ASYNC16(bd + 16, wsrc + 4);
    };

    float acc[4][4][4];
#pragma unroll
    for (int i = 0; i < 4; i++)
#pragma unroll
        for (int j = 0; j < 4; j++)
#pragma unroll
            for (int r = 0; r < 4; r++) acc[i][j][r] = 0.f;

    issue(0, 0);
    CP_COMMIT();
    __syncthreads();   // h1s visible to all warps

    const int lq = lane >> 2;
    const int lk = lane & 3;

#pragma unroll 1
    for (int kt = 0; kt < 16; kt++) {
        int buf = kt & 1;
        if (kt < 15) { issue(buf ^ 1, (kt + 1) * 16); CP_COMMIT(); CP_WAIT1(); }
        else CP_WAIT0();
        __syncthreads();

#pragma unroll
        for (int ks = 0; ks < 2; ks++) {
            int kk = kt * 16 + ks * 8 + lk;
            uint32_t af[4][4];
#pragma unroll
            for (int mf = 0; mf < 4; mf++) {
                const float* ap = &h1s[(wm * 64 + mf * 16 + lq) * L2PAD + kk];
                af[mf][0] = __float_as_uint(ap[0]);
                af[mf][1] = __float_as_uint(ap[8 * L2PAD]);
                af[mf][2] = __float_as_uint(ap[4]);
                af[mf][3] = __float_as_uint(ap[8 * L2PAD + 4]);
            }
            int kw = ks * 8 + lk;
            uint32_t bfr[4][2];
#pragma unroll
            for (int nf = 0; nf < 4; nf++) {
                const float* bp = &Ws[buf * 128 * TPAD + (wn * 32 + nf * 8 + lq) * TPAD + kw];
                bfr[nf][0] = __float_as_uint(bp[0]);
                bfr[nf][1] = __float_as_uint(bp[4]);
            }
#pragma unroll
            for (int mf = 0; mf < 4; mf++)
#pragma unroll
                for (int nf = 0; nf < 4; nf++)
                    mma_tf32(acc[mf][nf], af[mf], bfr[nf]);
        }
        __syncthreads();
    }

#pragma unroll
    for (int mf = 0; mf < 4; mf++) {
        size_t r0 = mBase + wm * 64 + mf * 16 + lq;
        float* y0 = Y + r0 * 256 + n0;
        float* y1 = y0 + 8 * 256;
#pragma unroll
        for (int nf = 0; nf < 4; nf++) {
            int col = wn * 32 + nf * 8 + 2 * lk;
            float b0 = biasS[col], b1 = biasS[col + 1];
            float v0 = tf32r(fmaxf(acc[mf][nf][0] + b0, 0.f));
            float v1 = tf32r(fmaxf(acc[mf][nf][1] + b1, 0.f));
            float v2 = tf32r(fmaxf(acc[mf][nf][2] + b0, 0.f));
            float v3 = tf32r(fmaxf(acc[mf][nf][3] + b1, 0.f));
            float2 p0 = {v0, v1};
            float2 p1 = {v2, v3};
            *(float2*)(y0 + col) = p0;
            *(float2*)(y1 + col) = p1;
        }
    }
}

// ==================== g4: tf32 GEMM + fused pairsum (atomic) ================
__global__ void __launch_bounds__(256, 2)
gmlp_l4(const float* __restrict__ X, const float* __restrict__ W,
        const float* __restrict__ bias, float* __restrict__ xg) {
    __shared__ __align__(16) float As[2][TBUF];
    __shared__ __align__(16) float Bs[2][TBUF];
    __shared__ float biasS[128];

    const int tid = threadIdx.x;
    const int wid = tid >> 5;
    const int lane = tid & 31;
    const int wm = wid >> 2;
    const int wn = wid & 3;
    const int n0 = blockIdx.x * 128;
    const size_t mBase = (size_t)blockIdx.y * 128;

    if (tid < 128) biasS[tid] = __ldg(&bias[n0 + tid]);

    const uint32_t aRaw = smem_u32(As);
    const uint32_t bRaw = smem_u32(Bs);
    const float* Xt = X + mBase * 256;
    const float* Wt = W + (size_t)n0 * 256;

    const int lr = tid >> 1;
    const int lh = tid & 1;

    auto issue = [&](int buf, int k0) {
        uint32_t ad = aRaw + buf * (TBUF * 4) + lr * (TPAD * 4) + lh * 32;
        uint32_t bd = bRaw + buf * (TBUF * 4) + lr * (TPAD * 4) + lh * 32;
        const float* xs = Xt + lr * 256 + k0 + lh * 8;
        const float* wsrc = Wt + lr * 256 + k0 + lh * 8;
        CP_ASYNC16(ad, xs);
        CP_ASYNC16(ad + 16, xs + 4);
        CP_ASYNC16(bd, wsrc);
        CP_ASYNC16(bd + 16, wsrc + 4);
    };

    float acc[4][4][4];
#pragma unroll
    for (int i = 0; i < 4; i++)
#pragma unroll
        for (int j = 0; j < 4; j++)
#pragma unroll
            for (int r = 0; r < 4; r++) acc[i][j][r] = 0.f;

    issue(0, 0);
    CP_COMMIT();

    const int lq = lane >> 2;
    const int lk = lane & 3;

#pragma unroll 1
    for (int kt = 0; kt < 16; kt++) {
        int buf = kt & 1;
        if (kt < 15) { issue(buf ^ 1, (kt + 1) * 16); CP_COMMIT(); CP_WAIT1(); }
        else CP_WAIT0();
        __syncthreads();

#pragma unroll
        for (int ks = 0; ks < 2; ks++) {
            int kk = ks * 8 + lk;
            uint32_t af[4][4];
#pragma unroll
            for (int mf = 0; mf < 4; mf++) {
                const float* ap = &As[buf][(wm * 64 + mf * 16 + lq) * TPAD + kk];
                af[mf][0] = __float_as_uint(ap[0]);
                af[mf][1] = __float_as_uint(ap[8 * TPAD]);
                af[mf][2] = __float_as_uint(ap[4]);
                af[mf][3] = __float_as_uint(ap[8 * TPAD + 4]);
            }
            uint32_t bfr[4][2];
#pragma unroll
            for (int nf = 0; nf < 4; nf++) {
                const float* bp = &Bs[buf][(wn * 32 + nf * 8 + lq) * TPAD + kk];
                bfr[nf][0] = __float_as_uint(bp[0]);
                bfr[nf][1] = __float_as_uint(bp[4]);
            }
#pragma unroll
            for (int mf = 0; mf < 4; mf++)
#pragma unroll
                for (int nf = 0; nf < 4; nf++)
                    mma_tf32(acc[mf][nf], af[mf], bfr[nf]);
        }
        __syncthreads();
    }

    // ---- fused pairsum epilogue ----
    int b0 = (int)(mBase / 625);
    int split = (b0 + 1) * 625;                 // global row where b increments
    bool hasSplit = split < (int)mBase + 128;

    float cs0[4][2], cs1[4][2];
#pragma unroll
    for (int nf = 0; nf < 4; nf++) { cs0[nf][0] = cs0[nf][1] = 0.f; cs1[nf][0] = cs1[nf][1] = 0.f; }

#pragma unroll
    for (int mf = 0; mf < 4; mf++) {
        int rA = (int)mBase + wm * 64 + mf * 16 + lq;
        int rB = rA + 8;
        bool pA = rA >= split;
        bool pB = rB >= split;
#pragma unroll
        for (int nf = 0; nf < 4; nf++) {
            int col = wn * 32 + nf * 8 + 2 * lk;
            float bb0 = biasS[col], bb1 = biasS[col + 1];
            float v0 = fmaxf(acc[mf][nf][0] + bb0, 0.f);
            float v1 = fmaxf(acc[mf][nf][1] + bb1, 0.f);
            float v2 = fmaxf(acc[mf][nf][2] + bb0, 0.f);
            float v3 = fmaxf(acc[mf][nf][3] + bb1, 0.f);
            if (pA) { cs1[nf][0] += v0; cs1[nf][1] += v1; }
            else    { cs0[nf][0] += v0; cs0[nf][1] += v1; }
            if (pB) { cs1[nf][0] += v2; cs1[nf][1] += v3; }
            else    { cs0[nf][0] += v2; cs0[nf][1] += v3; }
        }
    }
    // reduce over lq (lanes stride 4)
#pragma unroll
    for (int off = 4; off <= 16; off <<= 1) {
#pragma unroll
        for (int nf = 0; nf < 4; nf++) {
            cs0[nf][0] += __shfl_xor_sync(0xffffffffu, cs0[nf][0], off);
            cs0[nf][1] += __shfl_xor_sync(0xffffffffu, cs0[nf][1], off);
            cs1[nf][0] += __shfl_xor_sync(0xffffffffu, cs1[nf][0], off);
            cs1[nf][1] += __shfl_xor_sync(0xffffffffu, cs1[nf][1], off);
        }
    }
    if (lq == 0) {
#pragma unroll
        for (int nf = 0; nf < 4; nf++) {
#pragma unroll
            for (int p = 0; p < 2; p++) {
                int col = n0 + wn * 32 + nf * 8 + 2 * lk + p;
                atomicAdd(&xg[b0 * 256 + col], cs0[nf][p]);
                if (hasSplit) atomicAdd(&xg[(b0 + 1) * 256 + col], cs1[nf][p]);
            }
        }
    }
}

// -------------------- fp32 SGEMM (small f-layers) ---------------------------
__global__ void sgemm256(const float* __restrict__ X, const float* __restrict__ W,
                         const float* __restrict__ bias, float* __restrict__ out,
                         int doRelu) {
    __shared__ float Xs[16][128];
    __shared__ float Ws[16][64];
    int bm = blockIdx.y * 128;
    int bn = blockIdx.x * 64;
    int tid = threadIdx.x;
    int tx = tid & 15, ty = tid >> 4;
    float acc[8][4];
#pragma unroll
    for (int i = 0; i < 8; i++)
#pragma unroll
        for (int j = 0; j < 4; j++) acc[i][j] = 0.f;

    int r0 = tid >> 2;
    int c0 = (tid & 3) * 4;
    const float* Xp = X + (size_t)bm * 256;

    for (int k0 = 0; k0 < 256; k0 += 16) {
        float4 x0 = *(const float4*)(Xp + (size_t)r0 * 256 + k0 + c0);
        float4 x1 = *(const float4*)(Xp + (size_t)(r0 + 64) * 256 + k0 + c0);
        float4 wv = *(const float4*)(W + (size_t)(bn + r0) * 256 + k0 + c0);
        Xs[c0 + 0][r0] = x0.x; Xs[c0 + 1][r0] = x0.y; Xs[c0 + 2][r0] = x0.z; Xs[c0 + 3][r0] = x0.w;
        Xs[c0 + 0][r0 + 64] = x1.x; Xs[c0 + 1][r0 + 64] = x1.y; Xs[c0 + 2][r0 + 64] = x1.z; Xs[c0 + 3][r0 + 64] = x1.w;
        Ws[c0 + 0][r0] = wv.x; Ws[c0 + 1][r0] = wv.y; Ws[c0 + 2][r0] = wv.z; Ws[c0 + 3][r0] = wv.w;
        __syncthreads();
#pragma unroll
        for (int k = 0; k < 16; k++) {
            float4 a0 = *(const float4*)&Xs[k][ty * 8];
            float4 a1 = *(const float4*)&Xs[k][ty * 8 + 4];
            float4 b = *(const float4*)&Ws[k][tx * 4];
            acc[0][0] += a0.x * b.x; acc[0][1] += a0.x * b.y; acc[0][2] += a0.x * b.z; acc[0][3] += a0.x * b.w;
            acc[1][0] += a0.y * b.x; acc[1][1] += a0.y * b.y; acc[1][2] += a0.y * b.z; acc[1][3] += a0.y * b.w;
            acc[2][0] += a0.z * b.x; acc[2][1] += a0.z * b.y; acc[2][2] += a0.z * b.z; acc[2][3] += a0.z * b.w;
            acc[3][0] += a0.w * b.x; acc[3][1] += a0.w * b.y; acc[3][2] += a0.w * b.z; acc[3][3] += a0.w * b.w;
            acc[4][0] += a1.x * b.x; acc[4][1] += a1.x * b.y; acc[4][2] += a1.x * b.z; acc[4][3] += a1.x * b.w;
            acc[5][0] += a1.y * b.x; acc[5][1] += a1.y * b.y; acc[5][2] += a1.y * b.z; acc[5][3] += a1.y * b.w;
            acc[6][0] += a1.z * b.x; acc[6][1] += a1.z * b.y; acc[6][2] += a1.z * b.z; acc[6][3] += a1.z * b.w;
            acc[7][0] += a1.w * b.x; acc[7][1] += a1.w * b.y; acc[7][2] += a1.w * b.z; acc[7][3] += a1.w * b.w;
        }
        __syncthreads();
    }
    float4 bv = *(const float4*)&bias[bn + tx * 4];
#pragma unroll
    for (int i = 0; i < 8; i++) {
        int m = bm + ty * 8 + i;
        float4 v;
        v.x = acc[i][0] + bv.x; v.y = acc[i][1] + bv.y;
        v.z = acc[i][2] + bv.z; v.w = acc[i][3] + bv.w;
        if (doRelu) {
            v.x = fmaxf(v.x, 0.f); v.y = fmaxf(v.y, 0.f);
            v.z = fmaxf(v.z, 0.f); v.w = fmaxf(v.w, 0.f);
        }
        *(float4*)(out + (size_t)m * 256 + bn + tx * 4) = v;
    }
}

// -------------------- fc3 + log_softmax -------------------------------------
__global__ void fc3_k(const float* __restrict__ x, const float* __restrict__ w,
                      const float* __restrict__ bias, float* __restrict__ out) {
    int b = blockIdx.x;
    int tid = threadIdx.x; // 320
    int j = tid >> 5, lane = tid & 31;
    __shared__ float lg[10];
    __shared__ float lse;
    const float* xr = x + b * HID;
    const float* wr = w + j * HID;
    float s = 0.f;
    for (int k = lane; k < HID; k += 32) s += xr[k] * wr[k];
#pragma unroll
    for (int o = 16; o > 0; o >>= 1) s += __shfl_xor_sync(0xffffffffu, s, o);
    if (lane == 0) lg[j] = s + bias[j];
    __syncthreads();
    if (tid == 0) {
        float m = lg[0];
#pragma unroll
        for (int t = 1; t < 10; t++) m = fmaxf(m, lg[t]);
        float se = 0.f;
#pragma unroll
        for (int t = 0; t < 10; t++) se += expf(lg[t] - m);
        lse = m + logf(se);
    }
    __syncthreads();
    if (tid < 10) out[b * 10 + tid] = lg[tid] - lse;
}

// ---------------------------------------------------------------------------
extern "C" void kernel_launch(void* const* d_in, const int* in_sizes, int n_in,
                              void* d_out, int out_size) {
    const float* img = (const float*)d_in[0];
    const float* qst = (const float*)d_in[1];
    const float* cw[4] = {(const float*)d_in[2], (const float*)d_in[6], (const float*)d_in[10], (const float*)d_in[14]};
    const float* cb[4] = {(const float*)d_in[3], (const float*)d_in[7], (const float*)d_in[11], (const float*)d_in[15]};
    const float* bg[4] = {(const float*)d_in[4], (const float*)d_in[8], (const float*)d_in[12], (const float*)d_in[16]};
    const float* bb[4] = {(const float*)d_in[5], (const float*)d_in[9], (const float*)d_in[13], (const float*)d_in[17]};
    const float* g1w = (const float*)d_in[18]; const float* g1b = (const float*)d_in[19];
    const float* g2w = (const float*)d_in[20]; const float* g2b = (const float*)d_in[21];
    const float* g3w = (const float*)d_in[22]; const float* g3b = (const float*)d_in[23];
    const float* g4w = (const float*)d_in[24]; const float* g4b = (const float*)d_in[25];
    const float* f1w = (const float*)d_in[26]; const float* f1b = (const float*)d_in[27];
    const float* fc2w = (const float*)d_in[28]; const float* fc2b = (const float*)d_in[29];
    const float* fc3w = (const float*)d_in[30]; const float* fc3b = (const float*)d_in[31];
    float* out = (float*)d_out;

    float *buf1, *buf2, *buf3, *buf4, *obj, *A, *B, *Cb, *hA, *hB, *xg, *xf1, *xf2, *stats, *wt;
    double *psum, *psq;
    cudaGetSymbolAddress((void**)&buf1, g_buf1);
    cudaGetSymbolAddress((void**)&buf2, g_buf2);
    cudaGetSymbolAddress((void**)&buf3, g_buf3);
    cudaGetSymbolAddress((void**)&buf4, g_buf4);
    cudaGetSymbolAddress((void**)&obj, g_obj);
    cudaGetSymbolAddress((void**)&A, g_A);
    cudaGetSymbolAddress((void**)&B, g_B);
    cudaGetSymbolAddress((void**)&Cb, g_Cb);
    cudaGetSymbolAddress((void**)&hA, g_hA);
    cudaGetSymbolAddress((void**)&hB, g_hB);
    cudaGetSymbolAddress((void**)&xg, g_xg);
    cudaGetSymbolAddress((void**)&xf1, g_xf1);
    cudaGetSymbolAddress((void**)&xf2, g_xf2);
    cudaGetSymbolAddress((void**)&stats, g_stats);
    cudaGetSymbolAddress((void**)&psum, g_psum);
    cudaGetSymbolAddress((void**)&psq, g_psq);
    cudaGetSymbolAddress((void**)&wt, g_wt);

    static bool attrSet = false;
    if (!attrSet) {
        cudaFuncSetAttribute(gmlp_l2, cudaFuncAttributeMaxDynamicSharedMemorySize, GL2_SMEM);
        attrSet = true;
    }

    // ---- zero accumulators ----
    zerod_k<<<1, 128>>>(psum, 96);
    zerod_k<<<1, 128>>>(psq, 96);
    zerof_k<<<512, 256>>>(xg, BATCH * HID);

    // ---- weight prep (tf32 rounding) ----
    wtf32_k<<<256, 256>>>(g2w, wt);
    wtf32_k<<<256, 256>>>(g3w, wt + HID * HID);
    wtf32_k<<<256, 256>>>(g4w, wt + 2 * HID * HID);

    // ---- conv stack (fused BN) ----
    conv1_f<<<3200, 256>>>(img, cw[0], cb[0], buf1, psum, psq);
    bn_final_f<<<1, 32>>>(psum, psq, 512.0 * 1600.0, bg[0], stats);
    conv24_f<40, 20><<<800, 256>>>(buf1, cw[1], cb[1], stats, bb[0], buf2, psum + 24, psq + 24);
    bn_final_f<<<1, 32>>>(psum + 24, psq + 24, 512.0 * 400.0, bg[1], stats + 48);
    conv24_f<20, 10><<<200, 256>>>(buf2, cw[2], cb[2], stats + 48, bb[1], buf3, psum + 48, psq + 48);
    bn_final_f<<<1, 32>>>(psum + 48, psq + 48, 512.0 * 100.0, bg[2], stats + 96);
    conv24_f<10, 5><<<50, 256>>>(buf3, cw[3], cb[3], stats + 96, bb[2], buf4, psum + 72, psq + 72);
    bn_final_f<<<1, 32>>>(psum + 72, psq + 72, 512.0 * 25.0, bg[3], stats + 144);

    // ---- objects + decomposed g1 ----
    obj_f<<<(BATCH * OBJ * 26 + 255) / 256, 256>>>(buf4, stats + 144, bb[3], obj);
    ab_k<<<BATCH * OBJ, 256>>>(obj, g1w, A, B);
    cb_k<<<BATCH, 256>>>(qst, g1w, g1b, Cb);

    // ---- g2 (fused h1) -> g3 -> g4 (fused pairsum) ----
    dim3 ggrid(2, BATCH * OBJ * OBJ / 128);  // (2, 2500)
    gmlp_l2<<<ggrid, 256, GL2_SMEM>>>(A, B, Cb, wt, g2b, hB);
    gmlp_tf32<<<ggrid, 256>>>(hB, wt + HID * HID, g3b, hA, 1);
    gmlp_l4<<<ggrid, 256>>>(hA, wt + 2 * HID * HID, g4b, xg);

    // ---- f-MLP (fp32) ----
    dim3 fgrid(256 / 64, BATCH / 128);
    sgemm256<<<fgrid, 256>>>(xg, f1w, f1b, xf1, 1);
    sgemm256<<<fgrid, 256>>>(xf1, fc2w, fc2b, xf2, 1);
    fc3_k<<<BATCH, 320>>>(xf2, fc3w, fc3b, out);
}